// round 5
// baseline (speedup 1.0000x reference)
#include <cuda_runtime.h>
#include <cuda_bf16.h>
#include <cstdint>
#include <cstddef>

#define T_STEPS 100
#define BATCH   256
#define HID     1024
#define N_IN    4096

#define NCTA    128
#define THREADS 256
#define GROUPS  8          // batch groups (32 rows each) — independent dataflow domains
#define GSZ     16         // CTAs per group (N tiles)
#define MT      32         // batch rows per group
#define NT      64         // hidden cols per CTA
#define KC      256        // K chunk (cols) for staged cp.async
#define SW      1032       // smem row stride in bf16 (2064B -> conflict-free ldmatrix)
#define XW      68         // xs row stride in floats

// ---------------- device scratch ----------------
__device__ __nv_bfloat16 g_hidden[(size_t)(T_STEPS + 1) * BATCH * HID];
__device__ float         g_WxT[(size_t)N_IN * HID];     // Wx^T with (bm+bx) folded in
__device__ int           g_flags[T_STEPS * GROUPS * 4]; // chunk-ready counters (0..4)

// ---------------- helpers ----------------
__device__ __forceinline__ uint32_t smem_u32(const void* p) {
    return (uint32_t)__cvta_generic_to_shared(p);
}
__device__ __forceinline__ void ldmx4(uint32_t& r0, uint32_t& r1, uint32_t& r2, uint32_t& r3,
                                      uint32_t addr) {
    asm volatile("ldmatrix.sync.aligned.m8n8.x4.shared.b16 {%0,%1,%2,%3},[%4];\n"
                 : "=r"(r0), "=r"(r1), "=r"(r2), "=r"(r3) : "r"(addr));
}
__device__ __forceinline__ void ldmx2(uint32_t& r0, uint32_t& r1, uint32_t addr) {
    asm volatile("ldmatrix.sync.aligned.m8n8.x2.shared.b16 {%0,%1},[%2];\n"
                 : "=r"(r0), "=r"(r1) : "r"(addr));
}
__device__ __forceinline__ void mma16816(float* c, uint32_t a0, uint32_t a1, uint32_t a2,
                                         uint32_t a3, uint32_t b0, uint32_t b1) {
    asm volatile("mma.sync.aligned.m16n8k16.row.col.f32.bf16.bf16.f32 "
                 "{%0,%1,%2,%3},{%4,%5,%6,%7},{%8,%9},{%0,%1,%2,%3};\n"
                 : "+f"(c[0]), "+f"(c[1]), "+f"(c[2]), "+f"(c[3])
                 : "r"(a0), "r"(a1), "r"(a2), "r"(a3), "r"(b0), "r"(b1));
}
__device__ __forceinline__ void cp16(uint32_t dst, const void* src) {
    asm volatile("cp.async.cg.shared.global [%0],[%1],16;\n" :: "r"(dst), "l"(src));
}

// ---------------- prologue kernels ----------------
__global__ void prep_kernel(const float* __restrict__ b_start) {
    int i = blockIdx.x * blockDim.x + threadIdx.x;
    if (i < BATCH * HID)
        g_hidden[i] = __float2bfloat16(b_start[i & (HID - 1)]);  // h0 = b_start broadcast
    if (i < T_STEPS * GROUPS * 4)
        g_flags[i] = 0;                                          // reset dataflow flags
}

__global__ void transpose_wx(const float* __restrict__ Wx, const float* __restrict__ bm,
                             const float* __restrict__ bx) {
    __shared__ float tile[32][33];
    int x0 = blockIdx.x * 32;   // along N_IN
    int y0 = blockIdx.y * 32;   // along HID
    int tx = threadIdx.x;
    for (int i = threadIdx.y; i < 32; i += 8)
        tile[i][tx] = Wx[(size_t)(y0 + i) * N_IN + x0 + tx];
    __syncthreads();
    for (int i = threadIdx.y; i < 32; i += 8)
        g_WxT[(size_t)(x0 + i) * HID + y0 + tx] = tile[tx][i] + bm[y0 + tx] + bx[y0 + tx];
}

// ---------------- persistent RNN mainloop (dataflow-synced, no barriers) ----------------
__global__ void __launch_bounds__(THREADS, 1) rnn_kernel(const int* __restrict__ x_idx,
                                                         const float* __restrict__ Wm) {
    extern __shared__ __align__(16) char smem_raw[];
    __nv_bfloat16* wm_s = (__nv_bfloat16*)smem_raw;       // 64 x SW bf16 (resident Wm slab)
    __nv_bfloat16* a_s  = wm_s + NT * SW;                 // 32 x SW bf16 (full h tile)
    float*         xs   = (float*)(a_s + MT * SW);        // 32 x XW floats

    const int tid  = threadIdx.x;
    const int warp = tid >> 5, lane = tid & 31;
    const int grp = blockIdx.x >> 4;      // batch group (8)
    const int nt  = blockIdx.x & 15;      // N tile within group (16)
    const int m0 = grp * MT;
    const int n0 = nt * NT;

    // Load Wm slab rows [n0, n0+64) x K=1024, f32 -> bf16, resident for all steps.
    for (int i = tid; i < NT * 128; i += THREADS) {
        int r = i >> 7, c8 = i & 127;
        const float4* s = (const float4*)&Wm[(size_t)(n0 + r) * HID + c8 * 8];
        float4 f0 = s[0], f1 = s[1];
        uint32_t pk[4];
        ((__nv_bfloat162*)pk)[0] = __floats2bfloat162_rn(f0.x, f0.y);
        ((__nv_bfloat162*)pk)[1] = __floats2bfloat162_rn(f0.z, f0.w);
        ((__nv_bfloat162*)pk)[2] = __floats2bfloat162_rn(f1.x, f1.y);
        ((__nv_bfloat162*)pk)[3] = __floats2bfloat162_rn(f1.z, f1.w);
        *(uint4*)&wm_s[r * SW + c8 * 8] = *(uint4*)pk;
    }
    __syncthreads();

    // ldmatrix lane bases
    // A: rows 0-31 of the h tile; x4 frag: row = lane&15, k-half = lane>>4
    const uint32_t a_lane = smem_u32(a_s) +
        (uint32_t)(((lane & 15) * SW + ((lane >> 4) << 3)) * 2);
    // B: warp owns 8 n-rows [warp*8, warp*8+8); x2 frag: row = lane&7, k-half = (lane>>3)&1
    const uint32_t b_lane = smem_u32(wm_s) +
        (uint32_t)(((warp * 8 + (lane & 7)) * SW + (((lane >> 3) & 1) << 3)) * 2);

    // cp.async thread mapping: row = tid>>3, slot = tid&7 (64B per slot per chunk)
    const int cp_row  = tid >> 3;
    const int cp_slot = tid & 7;
    const uint32_t cp_dst_row = smem_u32(a_s) + (uint32_t)(cp_row * SW * 2);

    volatile int* flags_t = nullptr;

    for (int t = 0; t < T_STEPS; t++) {
        const __nv_bfloat16* hp = g_hidden + (size_t)t * BATCH * HID + (size_t)m0 * HID;
        if (t > 0) flags_t = (volatile int*)&g_flags[((t - 1) * GROUPS + grp) * 4];

        // Issue the 4 K-chunks; each gated on its producers' ready flag (dataflow sync).
        const __nv_bfloat16* rowp = hp + (size_t)cp_row * HID;
        #pragma unroll
        for (int ch = 0; ch < 4; ch++) {
            if (t > 0) {
                while (flags_t[ch] < 4) { }
                __threadfence();
            }
            #pragma unroll
            for (int q = 0; q < 4; q++) {
                int c8 = ch * 32 + cp_slot * 4 + q;      // 16B unit index within row
                cp16(cp_dst_row + (uint32_t)(c8 * 16), rowp + c8 * 8);
            }
            asm volatile("cp.async.commit_group;" ::: "memory");
        }

        // x projection gather (bias folded into g_WxT); overlaps chunk-0 arrival
        {
            const int r = tid >> 3, seg = tid & 7;
            int x = x_idx[t * BATCH + m0 + r];
            const float2* src = (const float2*)&g_WxT[(size_t)x * HID + n0 + seg * 8];
            float2* dst = (float2*)&xs[r * XW + seg * 8];
            dst[0] = src[0]; dst[1] = src[1]; dst[2] = src[2]; dst[3] = src[3];
        }

        float acc[2][4];
        #pragma unroll
        for (int i = 0; i < 2; i++)
            acc[i][0] = acc[i][1] = acc[i][2] = acc[i][3] = 0.f;

        #pragma unroll
        for (int ch = 0; ch < 4; ch++) {
            if (ch == 0)      asm volatile("cp.async.wait_group 3;" ::: "memory");
            else if (ch == 1) asm volatile("cp.async.wait_group 2;" ::: "memory");
            else if (ch == 2) asm volatile("cp.async.wait_group 1;" ::: "memory");
            else              asm volatile("cp.async.wait_group 0;" ::: "memory");
            __syncthreads();

            #pragma unroll
            for (int kk = 0; kk < KC; kk += 16) {
                const uint32_t kb = (uint32_t)((ch * KC + kk) * 2);
                uint32_t a0, a1, a2, a3, a4, a5, a6, a7, b0, b1;
                ldmx4(a0, a1, a2, a3, a_lane + kb);                          // rows 0-15
                ldmx4(a4, a5, a6, a7, a_lane + (uint32_t)(16 * SW * 2) + kb);// rows 16-31
                ldmx2(b0, b1, b_lane + kb);                                  // warp's 8 n-cols
                mma16816(acc[0], a0, a1, a2, a3, b0, b1);
                mma16816(acc[1], a4, a5, a6, a7, b0, b1);
            }
        }

        // epilogue: + xproj(+bias), tanh.approx, pack bf16, store h[t+1]
        __nv_bfloat16* hout = g_hidden + (size_t)(t + 1) * BATCH * HID;
        const int r_base = lane >> 2;
        const int col = warp * 8 + (lane & 3) * 2;       // within CTA's 64
        #pragma unroll
        for (int mi = 0; mi < 2; mi++) {
            #pragma unroll
            for (int half = 0; half < 2; half++) {
                int row = mi * 16 + r_base + half * 8;
                float v0 = acc[mi][half * 2 + 0] + xs[row * XW + col];
                float v1 = acc[mi][half * 2 + 1] + xs[row * XW + col + 1];
                asm("tanh.approx.f32 %0, %0;" : "+f"(v0));
                asm("tanh.approx.f32 %0, %0;" : "+f"(v1));
                *(__nv_bfloat162*)&hout[(size_t)(m0 + row) * HID + n0 + col] =
                    __floats2bfloat162_rn(v0, v1);
            }
        }

        // publish: this CTA's 64 cols belong to K-chunk (nt>>2) of the group's A tile
        __threadfence();
        __syncthreads();
        if (tid == 0)
            atomicAdd(&g_flags[(t * GROUPS + grp) * 4 + (nt >> 2)], 1);
    }
}

// ---------------- epilogue: logits / pred / loss ----------------
__global__ void logits_kernel(const int* __restrict__ y_idx, const float* __restrict__ truth,
                              const float* __restrict__ Wy, const float* __restrict__ by,
                              float* __restrict__ out) {
    int gw = (blockIdx.x * blockDim.x + threadIdx.x) >> 5;
    int lane = threadIdx.x & 31;
    if (gw >= T_STEPS * BATCH) return;
    int t = gw >> 8;
    int b = gw & 255;
    int y = y_idx[gw];
    const __nv_bfloat16* h = g_hidden + (size_t)(t + 1) * BATCH * HID + (size_t)b * HID;
    const float* wy = Wy + (size_t)y * HID;
    float acc = 0.f;
    #pragma unroll 4
    for (int k = lane; k < HID; k += 32)
        acc += __bfloat162float(h[k]) * wy[k];
    #pragma unroll
    for (int o = 16; o; o >>= 1) acc += __shfl_xor_sync(0xffffffffu, acc, o);
    if (lane == 0) {
        float logit = acc + by[y];
        float pred = 1.f / (1.f + expf(-logit));
        float tr = truth[gw];
        float lsp = fminf(logit, 0.f)  - log1pf(expf(-fabsf(logit)));
        float lsn = fminf(-logit, 0.f) - log1pf(expf(-fabsf(logit)));
        float loss = -(tr * lsp + (1.f - tr) * lsn);
        out[gw] = pred;
        out[T_STEPS * BATCH + gw] = loss;
    }
}

// ---------------- launch ----------------
extern "C" void kernel_launch(void* const* d_in, const int* in_sizes, int n_in,
                              void* d_out, int out_size) {
    (void)in_sizes; (void)n_in; (void)out_size;
    const int*   x_idx   = (const int*)d_in[0];
    const int*   y_idx   = (const int*)d_in[1];
    const float* truth   = (const float*)d_in[2];
    const float* Wm      = (const float*)d_in[3];
    const float* bm      = (const float*)d_in[4];
    const float* Wx      = (const float*)d_in[5];
    const float* bx      = (const float*)d_in[6];
    const float* Wy      = (const float*)d_in[7];
    const float* by      = (const float*)d_in[8];
    // d_in[9] = W_start: multiplied by zeros -> unused
    const float* b_start = (const float*)d_in[10];
    float* out = (float*)d_out;

    prep_kernel<<<(BATCH * HID + 255) / 256, 256>>>(b_start);
    transpose_wx<<<dim3(N_IN / 32, HID / 32), dim3(32, 8)>>>(Wx, bm, bx);

    const int smem_bytes = (NT * SW + MT * SW) * 2 + MT * XW * 4;   // ~207 KB
    cudaFuncSetAttribute(rnn_kernel, cudaFuncAttributeMaxDynamicSharedMemorySize, smem_bytes);
    rnn_kernel<<<NCTA, THREADS, smem_bytes>>>(x_idx, Wm);

    logits_kernel<<<(T_STEPS * BATCH * 32 + 255) / 256, 256>>>(y_idx, truth, Wy, by, out);
}

// round 6
// speedup vs baseline: 1.2050x; 1.2050x over previous
#include <cuda_runtime.h>
#include <cuda_bf16.h>
#include <cstdint>
#include <cstddef>

#define T_STEPS 100
#define BATCH   256
#define HID     1024
#define N_IN    4096

#define NCTA    128
#define THREADS 128
#define GROUPS  8          // batch groups (32 rows each) — independent sync domains
#define GSZ     16         // CTAs per group (N tiles)
#define MT      32         // batch rows per group
#define NT      64         // hidden cols per CTA
#define KC      256        // K chunk (cols) for staged cp.async
#define SW      1032       // smem row stride in bf16 (2064B -> conflict-free ldmatrix)
#define XW      68         // xs row stride in floats

// ---------------- device scratch ----------------
__device__ __nv_bfloat16 g_hidden[(size_t)(T_STEPS + 1) * BATCH * HID];
__device__ float         g_WxT[(size_t)N_IN * HID];        // Wx^T with (bm+bx) folded in
__device__ int           g_ready[(T_STEPS + 1) * GROUPS];  // per-step arrive counters
__device__ unsigned      g_count;                          // full-grid barrier (replay-safe)
__device__ unsigned      g_gen;

// ---------------- helpers ----------------
__device__ __forceinline__ uint32_t smem_u32(const void* p) {
    return (uint32_t)__cvta_generic_to_shared(p);
}
__device__ __forceinline__ void ldmx4(uint32_t& r0, uint32_t& r1, uint32_t& r2, uint32_t& r3,
                                      uint32_t addr) {
    asm volatile("ldmatrix.sync.aligned.m8n8.x4.shared.b16 {%0,%1,%2,%3},[%4];\n"
                 : "=r"(r0), "=r"(r1), "=r"(r2), "=r"(r3) : "r"(addr));
}
__device__ __forceinline__ void mma16816(float* c, uint32_t a0, uint32_t a1, uint32_t a2,
                                         uint32_t a3, uint32_t b0, uint32_t b1) {
    asm volatile("mma.sync.aligned.m16n8k16.row.col.f32.bf16.bf16.f32 "
                 "{%0,%1,%2,%3},{%4,%5,%6,%7},{%8,%9},{%0,%1,%2,%3};\n"
                 : "+f"(c[0]), "+f"(c[1]), "+f"(c[2]), "+f"(c[3])
                 : "r"(a0), "r"(a1), "r"(a2), "r"(a3), "r"(b0), "r"(b1));
}
__device__ __forceinline__ void cp16(uint32_t dst, const void* src) {
    asm volatile("cp.async.cg.shared.global [%0],[%1],16;\n" :: "r"(dst), "l"(src));
}
__device__ __forceinline__ int ld_acq(const int* p) {
    int v;
    asm volatile("ld.acquire.gpu.global.b32 %0,[%1];" : "=r"(v) : "l"(p) : "memory");
    return v;
}

__device__ __forceinline__ void grid_barrier(int tid) {
    __syncthreads();
    if (tid == 0) {
        __threadfence();
        unsigned gen = atomicAdd(&g_gen, 0u);
        unsigned old = atomicAdd(&g_count, 1u);
        if (old == NCTA - 1) {
            atomicExch(&g_count, 0u);
            __threadfence();
            atomicAdd(&g_gen, 1u);
        } else {
            while (*(volatile unsigned*)&g_gen == gen) { }
        }
        __threadfence();
    }
    __syncthreads();
}

// ---------------- single fused persistent kernel ----------------
__global__ void __launch_bounds__(THREADS, 1) rnn_kernel(
    const int* __restrict__ x_idx, const int* __restrict__ y_idx,
    const float* __restrict__ truth, const float* __restrict__ Wm,
    const float* __restrict__ bm, const float* __restrict__ Wx,
    const float* __restrict__ bx, const float* __restrict__ Wy,
    const float* __restrict__ by, const float* __restrict__ b_start,
    float* __restrict__ out) {
    extern __shared__ __align__(16) char smem_raw[];
    __nv_bfloat16* wm_s = (__nv_bfloat16*)smem_raw;       // 64 x SW bf16 (resident Wm slab)
    __nv_bfloat16* a_s  = wm_s + NT * SW;                 // 32 x SW bf16 (full h tile)
    float*         xs   = (float*)(a_s + MT * SW);        // 32 x XW floats (also xpose stage)

    const int tid  = threadIdx.x;
    const int warp = tid >> 5, lane = tid & 31;
    const int grp = blockIdx.x >> 4;      // batch group (8)
    const int nt  = blockIdx.x & 15;      // N tile within group (16)
    const int m0 = grp * MT;
    const int n0 = nt * NT;

    // ---- prologue: Wm slab -> smem bf16 (resident for all steps) ----
    for (int i = tid; i < NT * 128; i += THREADS) {
        int r = i >> 7, c8 = i & 127;
        const float4* s = (const float4*)&Wm[(size_t)(n0 + r) * HID + c8 * 8];
        float4 f0 = s[0], f1 = s[1];
        uint32_t pk[4];
        ((__nv_bfloat162*)pk)[0] = __floats2bfloat162_rn(f0.x, f0.y);
        ((__nv_bfloat162*)pk)[1] = __floats2bfloat162_rn(f0.z, f0.w);
        ((__nv_bfloat162*)pk)[2] = __floats2bfloat162_rn(f1.x, f1.y);
        ((__nv_bfloat162*)pk)[3] = __floats2bfloat162_rn(f1.z, f1.w);
        *(uint4*)&wm_s[r * SW + c8 * 8] = *(uint4*)pk;
    }

    // ---- prologue: h0 = b_start broadcast (this CTA's 32 rows x 64 cols) ----
    for (int i = tid; i < MT * (NT / 2); i += THREADS) {
        int r = i >> 5, c2 = i & 31;
        __nv_bfloat162 v = __floats2bfloat162_rn(b_start[n0 + c2 * 2],
                                                 b_start[n0 + c2 * 2 + 1]);
        *(__nv_bfloat162*)&g_hidden[(size_t)(m0 + r) * HID + n0 + c2 * 2] = v;
    }

    // ---- prologue: transpose Wx slice [x0, x0+32) with (bm+bx) folded ----
    {
        float (*tile)[33] = (float (*)[33])xs;
        int x0 = blockIdx.x * 32;
        int tx = lane, ty = warp;        // 32 x 4
        for (int yt = 0; yt < HID / 32; yt++) {
            int y0 = yt * 32;
            for (int i = ty; i < 32; i += 4)
                tile[i][tx] = Wx[(size_t)(y0 + i) * N_IN + x0 + tx];
            __syncthreads();
            for (int i = ty; i < 32; i += 4)
                g_WxT[(size_t)(x0 + i) * HID + y0 + tx] = tile[tx][i] + bm[y0 + tx] + bx[y0 + tx];
            __syncthreads();
        }
    }
    __threadfence();
    grid_barrier(tid);   // WxT + h0 visible everywhere

    // ldmatrix lane bases (identical to the proven R4 layout)
    const uint32_t a_lane = smem_u32(a_s) +
        (uint32_t)(((lane & 15) * SW + ((lane >> 4) << 3)) * 2);
    const uint32_t b_lane = smem_u32(wm_s) +
        (uint32_t)(((warp * 16 + (lane & 15)) * SW + ((lane >> 4) << 3)) * 2);
    const int cp_row = tid >> 2, cp_q4 = tid & 3;
    const uint32_t cp_dst_row = smem_u32(a_s) + (uint32_t)(cp_row * SW * 2);

    // ---- mainloop ----
    for (int t = 0; t < T_STEPS; t++) {
        // x projection gather FIRST (no dependence on peers) — hides part of the wait
        {
            const int r = tid >> 2, seg = tid & 3;
            int x = x_idx[t * BATCH + m0 + r];
            const float4* src = (const float4*)&g_WxT[(size_t)x * HID + n0 + seg * 16];
            float4* dst = (float4*)&xs[r * XW + seg * 16];
            dst[0] = src[0]; dst[1] = src[1]; dst[2] = src[2]; dst[3] = src[3];
        }

        // wait for the group's h[t] to be fully published (tid 0 only, acquire)
        if (t > 0) {
            if (tid == 0) {
                const int* f = &g_ready[t * GROUPS + grp];
                while (ld_acq(f) < GSZ) { }
            }
            __syncthreads();
        }

        // issue all 4 K-chunks of the A tile (32 x 1024), one commit per chunk
        const __nv_bfloat16* rowp = g_hidden + (size_t)t * BATCH * HID
                                  + (size_t)(m0 + cp_row) * HID;
        #pragma unroll
        for (int ch = 0; ch < 4; ch++) {
            #pragma unroll
            for (int q = 0; q < 8; q++) {
                int c8 = ch * 32 + cp_q4 * 8 + q;
                cp16(cp_dst_row + (uint32_t)(c8 * 16), rowp + c8 * 8);
            }
            asm volatile("cp.async.commit_group;" ::: "memory");
        }

        float acc[2][2][4];
        #pragma unroll
        for (int i = 0; i < 2; i++)
            #pragma unroll
            for (int j = 0; j < 2; j++)
                acc[i][j][0] = acc[i][j][1] = acc[i][j][2] = acc[i][j][3] = 0.f;

        #pragma unroll
        for (int ch = 0; ch < 4; ch++) {
            if (ch == 0)      asm volatile("cp.async.wait_group 3;" ::: "memory");
            else if (ch == 1) asm volatile("cp.async.wait_group 2;" ::: "memory");
            else if (ch == 2) asm volatile("cp.async.wait_group 1;" ::: "memory");
            else              asm volatile("cp.async.wait_group 0;" ::: "memory");
            __syncthreads();

            #pragma unroll
            for (int kk = 0; kk < KC; kk += 16) {
                const uint32_t kb = (uint32_t)((ch * KC + kk) * 2);
                uint32_t a0, a1, a2, a3, a4, a5, a6, a7, b0, b1, b2, b3;
                ldmx4(a0, a1, a2, a3, a_lane + kb);                           // rows 0-15
                ldmx4(a4, a5, a6, a7, a_lane + (uint32_t)(16 * SW * 2) + kb); // rows 16-31
                ldmx4(b0, b1, b2, b3, b_lane + kb);                           // 16 n-cols
                mma16816(acc[0][0], a0, a1, a2, a3, b0, b2);
                mma16816(acc[0][1], a0, a1, a2, a3, b1, b3);
                mma16816(acc[1][0], a4, a5, a6, a7, b0, b2);
                mma16816(acc[1][1], a4, a5, a6, a7, b1, b3);
            }
        }

        // epilogue: + xproj(+bias), tanh.approx, pack bf16, store h[t+1]
        __nv_bfloat16* hout = g_hidden + (size_t)(t + 1) * BATCH * HID;
        const int r_base = lane >> 2;
        const int c_base = (lane & 3) * 2;
        #pragma unroll
        for (int mi = 0; mi < 2; mi++) {
            #pragma unroll
            for (int ni = 0; ni < 2; ni++) {
                int col = warp * 16 + ni * 8 + c_base;
                #pragma unroll
                for (int half = 0; half < 2; half++) {
                    int row = mi * 16 + r_base + half * 8;
                    float v0 = acc[mi][ni][half * 2 + 0] + xs[row * XW + col];
                    float v1 = acc[mi][ni][half * 2 + 1] + xs[row * XW + col + 1];
                    asm("tanh.approx.f32 %0, %0;" : "+f"(v0));
                    asm("tanh.approx.f32 %0, %0;" : "+f"(v1));
                    *(__nv_bfloat162*)&hout[(size_t)(m0 + row) * HID + n0 + col] =
                        __floats2bfloat162_rn(v0, v1);
                }
            }
        }

        // publish h[t+1] slice (arrive-only; no blocking — skew pipelines away)
        __threadfence();
        __syncthreads();
        if (tid == 0)
            atomicAdd(&g_ready[(t + 1) * GROUPS + grp], 1);
    }

    // ---- fused logits / pred / loss (group-local rows) ----
    if (tid == 0) {
        const int* f = &g_ready[T_STEPS * GROUPS + grp];
        while (ld_acq(f) < GSZ) { }
    }
    __syncthreads();

    for (int i = 0; i < 50; i++) {
        int j  = nt * 200 + warp * 50 + i;   // 0..3199 within group
        int t  = j >> 5;
        int bl = j & 31;
        int gw = t * BATCH + m0 + bl;
        int y  = y_idx[gw];
        const __nv_bfloat16* h = g_hidden + (size_t)(t + 1) * BATCH * HID
                               + (size_t)(m0 + bl) * HID;
        const float* wy = Wy + (size_t)y * HID;
        float acc = 0.f;
        #pragma unroll
        for (int p = 0; p < 4; p++) {
            int k = p * 256 + lane * 8;
            uint4 hv = *(const uint4*)(h + k);
            const float4* w4 = (const float4*)(wy + k);
            float4 w0 = w4[0], w1 = w4[1];
            const __nv_bfloat162* hb = (const __nv_bfloat162*)&hv;
            float2 f0 = __bfloat1622float2(hb[0]);
            float2 f1 = __bfloat1622float2(hb[1]);
            float2 f2 = __bfloat1622float2(hb[2]);
            float2 f3 = __bfloat1622float2(hb[3]);
            acc += f0.x * w0.x + f0.y * w0.y + f1.x * w0.z + f1.y * w0.w
                 + f2.x * w1.x + f2.y * w1.y + f3.x * w1.z + f3.y * w1.w;
        }
        #pragma unroll
        for (int o = 16; o; o >>= 1) acc += __shfl_xor_sync(0xffffffffu, acc, o);
        if (lane == 0) {
            float logit = acc + by[y];
            float pred = 1.f / (1.f + expf(-logit));
            float tr = truth[gw];
            float lsp = fminf(logit, 0.f)  - log1pf(expf(-fabsf(logit)));
            float lsn = fminf(-logit, 0.f) - log1pf(expf(-fabsf(logit)));
            out[gw] = pred;
            out[T_STEPS * BATCH + gw] = -(tr * lsp + (1.f - tr) * lsn);
        }
    }

    // ---- reset arrive counters for the next graph replay ----
    grid_barrier(tid);     // nobody still polling
    for (int i = blockIdx.x * THREADS + tid; i < (T_STEPS + 1) * GROUPS; i += NCTA * THREADS)
        g_ready[i] = 0;
    __threadfence();
    grid_barrier(tid);     // resets visible before exit
}

// ---------------- launch ----------------
extern "C" void kernel_launch(void* const* d_in, const int* in_sizes, int n_in,
                              void* d_out, int out_size) {
    (void)in_sizes; (void)n_in; (void)out_size;
    const int*   x_idx   = (const int*)d_in[0];
    const int*   y_idx   = (const int*)d_in[1];
    const float* truth   = (const float*)d_in[2];
    const float* Wm      = (const float*)d_in[3];
    const float* bm      = (const float*)d_in[4];
    const float* Wx      = (const float*)d_in[5];
    const float* bx      = (const float*)d_in[6];
    const float* Wy      = (const float*)d_in[7];
    const float* by      = (const float*)d_in[8];
    // d_in[9] = W_start: multiplied by zeros -> unused
    const float* b_start = (const float*)d_in[10];
    float* out = (float*)d_out;

    const int smem_bytes = (NT * SW + MT * SW) * 2 + MT * XW * 4;   // ~207 KB
    cudaFuncSetAttribute(rnn_kernel, cudaFuncAttributeMaxDynamicSharedMemorySize, smem_bytes);
    rnn_kernel<<<NCTA, THREADS, smem_bytes>>>(x_idx, y_idx, truth, Wm, bm, Wx, bx,
                                              Wy, by, b_start, out);
}

// round 7
// speedup vs baseline: 1.2500x; 1.0374x over previous
#include <cuda_runtime.h>
#include <cuda_bf16.h>
#include <cstdint>
#include <cstddef>

#define T_STEPS 100
#define BATCH   256
#define HID     1024
#define N_IN    4096

#define NCTA    128
#define THREADS 256
#define GROUPS  8          // batch groups (32 rows each) — independent sync domains
#define GSZ     16         // CTAs per group (N tiles)
#define MT      32         // batch rows per group
#define NT      64         // hidden cols per CTA
#define KC      256        // K chunk (cols)
#define SW      1032       // smem row stride in bf16 (2064B -> conflict-free ldmatrix)
#define XW      68         // xs row stride in floats

// ---------------- device scratch ----------------
__device__ __nv_bfloat16 g_hidden[(size_t)(T_STEPS + 1) * BATCH * HID];
__device__ float         g_WxT[(size_t)N_IN * HID];        // Wx^T with (bm+bx) folded in
__device__ int           g_ready[(T_STEPS + 1) * GROUPS];  // per-step arrive counters
__device__ unsigned      g_count;                          // full-grid barrier (replay-safe)
__device__ unsigned      g_gen;

// ---------------- helpers ----------------
__device__ __forceinline__ uint32_t smem_u32(const void* p) {
    return (uint32_t)__cvta_generic_to_shared(p);
}
__device__ __forceinline__ void ldmx4(uint32_t& r0, uint32_t& r1, uint32_t& r2, uint32_t& r3,
                                      uint32_t addr) {
    asm volatile("ldmatrix.sync.aligned.m8n8.x4.shared.b16 {%0,%1,%2,%3},[%4];\n"
                 : "=r"(r0), "=r"(r1), "=r"(r2), "=r"(r3) : "r"(addr));
}
__device__ __forceinline__ void mma16816(float* c, uint32_t a0, uint32_t a1, uint32_t a2,
                                         uint32_t a3, uint32_t b0, uint32_t b1) {
    asm volatile("mma.sync.aligned.m16n8k16.row.col.f32.bf16.bf16.f32 "
                 "{%0,%1,%2,%3},{%4,%5,%6,%7},{%8,%9},{%0,%1,%2,%3};\n"
                 : "+f"(c[0]), "+f"(c[1]), "+f"(c[2]), "+f"(c[3])
                 : "r"(a0), "r"(a1), "r"(a2), "r"(a3), "r"(b0), "r"(b1));
}
__device__ __forceinline__ void cp16(uint32_t dst, const void* src) {
    asm volatile("cp.async.cg.shared.global [%0],[%1],16;\n" :: "r"(dst), "l"(src));
}
__device__ __forceinline__ int ld_acq(const int* p) {
    int v;
    asm volatile("ld.acquire.gpu.global.b32 %0,[%1];" : "=r"(v) : "l"(p) : "memory");
    return v;
}
__device__ __forceinline__ void bar_named(int id) {
    asm volatile("bar.sync %0, 128;" :: "r"(id) : "memory");
}

__device__ __forceinline__ void grid_barrier(int tid) {
    __syncthreads();
    if (tid == 0) {
        __threadfence();
        unsigned gen = atomicAdd(&g_gen, 0u);
        unsigned old = atomicAdd(&g_count, 1u);
        if (old == NCTA - 1) {
            atomicExch(&g_count, 0u);
            __threadfence();
            atomicAdd(&g_gen, 1u);
        } else {
            while (*(volatile unsigned*)&g_gen == gen) { }
        }
        __threadfence();
    }
    __syncthreads();
}

// ---------------- single fused persistent kernel ----------------
__global__ void __launch_bounds__(THREADS, 1) rnn_kernel(
    const int* __restrict__ x_idx, const int* __restrict__ y_idx,
    const float* __restrict__ truth, const float* __restrict__ Wm,
    const float* __restrict__ bm, const float* __restrict__ Wx,
    const float* __restrict__ bx, const float* __restrict__ Wy,
    const float* __restrict__ by, const float* __restrict__ b_start,
    float* __restrict__ out) {
    extern __shared__ __align__(16) char smem_raw[];
    __nv_bfloat16* wm_s = (__nv_bfloat16*)smem_raw;       // 64 x SW bf16 (resident Wm slab)
    __nv_bfloat16* a_s  = wm_s + NT * SW;                 // 32 x SW bf16 (full h tile)
    float*         xs   = (float*)(a_s + MT * SW);        // 32 x XW floats (also xpose stage)
    float*         red  = (float*)a_s;                    // reduction buf (reuses dead A region)

    const int tid  = threadIdx.x;
    const int warp = tid >> 5, lane = tid & 31;
    const int wg    = warp >> 2;       // warpgroup: 0 -> K[0,512), 1 -> K[512,1024)
    const int wwarp = warp & 3;        // warp within group (owns 16 N cols)
    const int wtid  = tid & 127;
    const int barid = 1 + wg;
    const int grp = blockIdx.x >> 4;   // batch group (8)
    const int nt  = blockIdx.x & 15;   // N tile within group (16)
    const int m0 = grp * MT;
    const int n0 = nt * NT;

    // ---- prologue: Wm slab -> smem bf16 (resident for all steps) ----
    for (int i = tid; i < NT * 128; i += THREADS) {
        int r = i >> 7, c8 = i & 127;
        const float4* s = (const float4*)&Wm[(size_t)(n0 + r) * HID + c8 * 8];
        float4 f0 = s[0], f1 = s[1];
        uint32_t pk[4];
        ((__nv_bfloat162*)pk)[0] = __floats2bfloat162_rn(f0.x, f0.y);
        ((__nv_bfloat162*)pk)[1] = __floats2bfloat162_rn(f0.z, f0.w);
        ((__nv_bfloat162*)pk)[2] = __floats2bfloat162_rn(f1.x, f1.y);
        ((__nv_bfloat162*)pk)[3] = __floats2bfloat162_rn(f1.z, f1.w);
        *(uint4*)&wm_s[r * SW + c8 * 8] = *(uint4*)pk;
    }

    // ---- prologue: h0 = b_start broadcast (this CTA's 32 rows x 64 cols) ----
    for (int i = tid; i < MT * (NT / 2); i += THREADS) {
        int r = i >> 5, c2 = i & 31;
        __nv_bfloat162 v = __floats2bfloat162_rn(b_start[n0 + c2 * 2],
                                                 b_start[n0 + c2 * 2 + 1]);
        *(__nv_bfloat162*)&g_hidden[(size_t)(m0 + r) * HID + n0 + c2 * 2] = v;
    }

    // ---- prologue: transpose Wx slice [x0, x0+32) with (bm+bx) folded ----
    {
        float (*tile)[33] = (float (*)[33])xs;
        int x0 = blockIdx.x * 32;
        int tx = lane, ty = warp;        // 32 x 8
        for (int yt = 0; yt < HID / 32; yt++) {
            int y0 = yt * 32;
            for (int i = ty; i < 32; i += 8)
                tile[i][tx] = Wx[(size_t)(y0 + i) * N_IN + x0 + tx];
            __syncthreads();
            for (int i = ty; i < 32; i += 8)
                g_WxT[(size_t)(x0 + i) * HID + y0 + tx] = tile[tx][i] + bm[y0 + tx] + bx[y0 + tx];
            __syncthreads();
        }
    }
    __threadfence();
    grid_barrier(tid);   // WxT + h0 visible everywhere

    // ldmatrix lane bases (R4 fragment shape, per warp: M32 x N16)
    const uint32_t a_lane = smem_u32(a_s) +
        (uint32_t)(((lane & 15) * SW + ((lane >> 4) << 3)) * 2);
    const uint32_t b_lane = smem_u32(wm_s) +
        (uint32_t)(((wwarp * 16 + (lane & 15)) * SW + ((lane >> 4) << 3)) * 2);
    const int cp_row = wtid >> 2, cp_q4 = wtid & 3;
    const uint32_t cp_dst_row = smem_u32(a_s) + (uint32_t)(cp_row * SW * 2);

    // ---- mainloop ----
    for (int t = 0; t < T_STEPS; t++) {
        // x projection gather FIRST (hides part of the dataflow wait)
        {
            const int r = tid >> 3, seg = tid & 7;
            int x = x_idx[t * BATCH + m0 + r];
            const float2* src = (const float2*)&g_WxT[(size_t)x * HID + n0 + seg * 8];
            float2* dst = (float2*)&xs[r * XW + seg * 8];
            dst[0] = src[0]; dst[1] = src[1]; dst[2] = src[2]; dst[3] = src[3];
        }

        // wait for the group's h[t] to be fully published (tid 0 only, acquire)
        if (t > 0 && tid == 0) {
            const int* f = &g_ready[t * GROUPS + grp];
            while (ld_acq(f) < GSZ) { }
        }
        __syncthreads();   // broadcast wait; also fences prev-step red/epilogue vs new cp.async

        // each warpgroup loads ITS 2 K-chunks of the A tile
        const __nv_bfloat16* rowp = g_hidden + (size_t)t * BATCH * HID
                                  + (size_t)(m0 + cp_row) * HID;
        #pragma unroll
        for (int c = 0; c < 2; c++) {
            int gch = wg * 2 + c;
            #pragma unroll
            for (int q = 0; q < 8; q++) {
                int c8 = gch * 32 + cp_q4 * 8 + q;
                cp16(cp_dst_row + (uint32_t)(c8 * 16), rowp + c8 * 8);
            }
            asm volatile("cp.async.commit_group;" ::: "memory");
        }

        float acc[2][2][4];
        #pragma unroll
        for (int i = 0; i < 2; i++)
            #pragma unroll
            for (int j = 0; j < 2; j++)
                acc[i][j][0] = acc[i][j][1] = acc[i][j][2] = acc[i][j][3] = 0.f;

        #pragma unroll
        for (int c = 0; c < 2; c++) {
            if (c == 0) asm volatile("cp.async.wait_group 1;" ::: "memory");
            else        asm volatile("cp.async.wait_group 0;" ::: "memory");
            bar_named(barid);   // warpgroup-local producer/consumer sync

            #pragma unroll
            for (int kk = 0; kk < KC; kk += 16) {
                const uint32_t kb = (uint32_t)(((wg * 2 + c) * KC + kk) * 2);
                uint32_t a0, a1, a2, a3, a4, a5, a6, a7, b0, b1, b2, b3;
                ldmx4(a0, a1, a2, a3, a_lane + kb);                           // rows 0-15
                ldmx4(a4, a5, a6, a7, a_lane + (uint32_t)(16 * SW * 2) + kb); // rows 16-31
                ldmx4(b0, b1, b2, b3, b_lane + kb);                           // 16 n-cols
                mma16816(acc[0][0], a0, a1, a2, a3, b0, b2);
                mma16816(acc[0][1], a0, a1, a2, a3, b1, b3);
                mma16816(acc[1][0], a4, a5, a6, a7, b0, b2);
                mma16816(acc[1][1], a4, a5, a6, a7, b1, b3);
            }
        }

        // K-split reduction: wg1 publishes partial sums, wg0 adds + epilogue
        __syncthreads();
        float* af = &acc[0][0][0];
        if (wg == 1) {
            #pragma unroll
            for (int j = 0; j < 16; j++) red[j * 128 + wtid] = af[j];
        }
        __syncthreads();
        if (wg == 0) {
            #pragma unroll
            for (int j = 0; j < 16; j++) af[j] += red[j * 128 + wtid];

            // epilogue: + xproj(+bias), tanh.approx, pack bf16, store h[t+1]
            __nv_bfloat16* hout = g_hidden + (size_t)(t + 1) * BATCH * HID;
            const int r_base = lane >> 2;
            const int c_base = (lane & 3) * 2;
            #pragma unroll
            for (int mi = 0; mi < 2; mi++) {
                #pragma unroll
                for (int ni = 0; ni < 2; ni++) {
                    int col = wwarp * 16 + ni * 8 + c_base;
                    #pragma unroll
                    for (int half = 0; half < 2; half++) {
                        int row = mi * 16 + r_base + half * 8;
                        float v0 = acc[mi][ni][half * 2 + 0] + xs[row * XW + col];
                        float v1 = acc[mi][ni][half * 2 + 1] + xs[row * XW + col + 1];
                        asm("tanh.approx.f32 %0, %0;" : "+f"(v0));
                        asm("tanh.approx.f32 %0, %0;" : "+f"(v1));
                        *(__nv_bfloat162*)&hout[(size_t)(m0 + row) * HID + n0 + col] =
                            __floats2bfloat162_rn(v0, v1);
                    }
                }
            }
        }

        // publish h[t+1] slice (arrive-only; skew pipelines away)
        __threadfence();
        __syncthreads();
        if (tid == 0)
            atomicAdd(&g_ready[(t + 1) * GROUPS + grp], 1);
    }

    // ---- fused logits / pred / loss (group-local rows) ----
    if (tid == 0) {
        const int* f = &g_ready[T_STEPS * GROUPS + grp];
        while (ld_acq(f) < GSZ) { }
    }
    __syncthreads();

    for (int i = 0; i < 25; i++) {
        int j  = nt * 200 + warp * 25 + i;   // 0..3199 within group
        int t  = j >> 5;
        int bl = j & 31;
        int gw = t * BATCH + m0 + bl;
        int y  = y_idx[gw];
        const __nv_bfloat16* h = g_hidden + (size_t)(t + 1) * BATCH * HID
                               + (size_t)(m0 + bl) * HID;
        const float* wy = Wy + (size_t)y * HID;
        float acc = 0.f;
        #pragma unroll
        for (int p = 0; p < 4; p++) {
            int k = p * 256 + lane * 8;
            uint4 hv = *(const uint4*)(h + k);
            const float4* w4 = (const float4*)(wy + k);
            float4 w0 = w4[0], w1 = w4[1];
            const __nv_bfloat162* hb = (const __nv_bfloat162*)&hv;
            float2 f0 = __bfloat1622float2(hb[0]);
            float2 f1 = __bfloat1622float2(hb[1]);
            float2 f2 = __bfloat1622float2(hb[2]);
            float2 f3 = __bfloat1622float2(hb[3]);
            acc += f0.x * w0.x + f0.y * w0.y + f1.x * w0.z + f1.y * w0.w
                 + f2.x * w1.x + f2.y * w1.y + f3.x * w1.z + f3.y * w1.w;
        }
        #pragma unroll
        for (int o = 16; o; o >>= 1) acc += __shfl_xor_sync(0xffffffffu, acc, o);
        if (lane == 0) {
            float logit = acc + by[y];
            float pred = 1.f / (1.f + expf(-logit));
            float tr = truth[gw];
            float lsp = fminf(logit, 0.f)  - log1pf(expf(-fabsf(logit)));
            float lsn = fminf(-logit, 0.f) - log1pf(expf(-fabsf(logit)));
            out[gw] = pred;
            out[T_STEPS * BATCH + gw] = -(tr * lsp + (1.f - tr) * lsn);
        }
    }

    // ---- reset arrive counters for the next graph replay ----
    grid_barrier(tid);     // nobody still polling
    for (int i = blockIdx.x * THREADS + tid; i < (T_STEPS + 1) * GROUPS; i += NCTA * THREADS)
        g_ready[i] = 0;
    __threadfence();
    grid_barrier(tid);     // resets visible before exit
}

// ---------------- launch ----------------
extern "C" void kernel_launch(void* const* d_in, const int* in_sizes, int n_in,
                              void* d_out, int out_size) {
    (void)in_sizes; (void)n_in; (void)out_size;
    const int*   x_idx   = (const int*)d_in[0];
    const int*   y_idx   = (const int*)d_in[1];
    const float* truth   = (const float*)d_in[2];
    const float* Wm      = (const float*)d_in[3];
    const float* bm      = (const float*)d_in[4];
    const float* Wx      = (const float*)d_in[5];
    const float* bx      = (const float*)d_in[6];
    const float* Wy      = (const float*)d_in[7];
    const float* by      = (const float*)d_in[8];
    // d_in[9] = W_start: multiplied by zeros -> unused
    const float* b_start = (const float*)d_in[10];
    float* out = (float*)d_out;

    const int smem_bytes = (NT * SW + MT * SW) * 2 + MT * XW * 4;   // ~207 KB
    cudaFuncSetAttribute(rnn_kernel, cudaFuncAttributeMaxDynamicSharedMemorySize, smem_bytes);
    rnn_kernel<<<NCTA, THREADS, smem_bytes>>>(x_idx, y_idx, truth, Wm, bm, Wx, bx,
                                              Wy, by, b_start, out);
}

// round 8
// speedup vs baseline: 1.3168x; 1.0534x over previous
#include <cuda_runtime.h>
#include <cuda_bf16.h>
#include <cstdint>
#include <cstddef>

#define T_STEPS 100
#define BATCH   256
#define HID     1024
#define N_IN    4096

#define NCTA    128
#define THREADS 256
#define GROUPS  8          // batch groups (32 rows each)
#define GSZ     16         // CTAs per group (N tiles)
#define MT      32         // batch rows per group
#define NT      64         // hidden cols per CTA
#define KC      256        // K chunk (cols)
#define SW      1032       // smem row stride in bf16 (2064B -> conflict-free ldmatrix)
#define XW      68         // xs row stride in floats

// ---------------- device scratch ----------------
__device__ __nv_bfloat16 g_hidden[(size_t)(T_STEPS + 1) * BATCH * HID];
__device__ float         g_WxT[(size_t)N_IN * HID];             // Wx^T with (bm+bx) folded
__device__ int           g_ready[(T_STEPS + 1) * GROUPS * 4];   // per-chunk arrive counters
__device__ unsigned      g_count;                               // full-grid barrier
__device__ unsigned      g_gen;

// ---------------- helpers ----------------
__device__ __forceinline__ uint32_t smem_u32(const void* p) {
    return (uint32_t)__cvta_generic_to_shared(p);
}
__device__ __forceinline__ void ldmx4(uint32_t& r0, uint32_t& r1, uint32_t& r2, uint32_t& r3,
                                      uint32_t addr) {
    asm volatile("ldmatrix.sync.aligned.m8n8.x4.shared.b16 {%0,%1,%2,%3},[%4];\n"
                 : "=r"(r0), "=r"(r1), "=r"(r2), "=r"(r3) : "r"(addr));
}
__device__ __forceinline__ void mma16816(float* c, uint32_t a0, uint32_t a1, uint32_t a2,
                                         uint32_t a3, uint32_t b0, uint32_t b1) {
    asm volatile("mma.sync.aligned.m16n8k16.row.col.f32.bf16.bf16.f32 "
                 "{%0,%1,%2,%3},{%4,%5,%6,%7},{%8,%9},{%0,%1,%2,%3};\n"
                 : "+f"(c[0]), "+f"(c[1]), "+f"(c[2]), "+f"(c[3])
                 : "r"(a0), "r"(a1), "r"(a2), "r"(a3), "r"(b0), "r"(b1));
}
__device__ __forceinline__ void cp16(uint32_t dst, const void* src) {
    asm volatile("cp.async.cg.shared.global [%0],[%1],16;\n" :: "r"(dst), "l"(src));
}
__device__ __forceinline__ int ld_acq(const int* p) {
    int v;
    asm volatile("ld.acquire.gpu.global.b32 %0,[%1];" : "=r"(v) : "l"(p) : "memory");
    return v;
}
__device__ __forceinline__ void bar_named(int id) {
    asm volatile("bar.sync %0, 128;" :: "r"(id) : "memory");
}

__device__ __forceinline__ void grid_barrier(int tid) {
    __syncthreads();
    if (tid == 0) {
        __threadfence();
        unsigned gen = atomicAdd(&g_gen, 0u);
        unsigned old = atomicAdd(&g_count, 1u);
        if (old == NCTA - 1) {
            atomicExch(&g_count, 0u);
            __threadfence();
            atomicAdd(&g_gen, 1u);
        } else {
            while (*(volatile unsigned*)&g_gen == gen) { }
        }
        __threadfence();
    }
    __syncthreads();
}

// ---------------- single fused persistent kernel ----------------
__global__ void __launch_bounds__(THREADS, 1) rnn_kernel(
    const int* __restrict__ x_idx, const int* __restrict__ y_idx,
    const float* __restrict__ truth, const float* __restrict__ Wm,
    const float* __restrict__ bm, const float* __restrict__ Wx,
    const float* __restrict__ bx, const float* __restrict__ Wy,
    const float* __restrict__ by, const float* __restrict__ b_start,
    float* __restrict__ out) {
    extern __shared__ __align__(16) char smem_raw[];
    __nv_bfloat16* wm_s = (__nv_bfloat16*)smem_raw;       // 64 x SW bf16 (resident Wm slab)
    __nv_bfloat16* a_s  = wm_s + NT * SW;                 // 32 x SW bf16 (full h tile)
    float*         xs   = (float*)(a_s + MT * SW);        // 32 x XW floats (+xpose stage)
    float*         red  = xs + MT * XW;                   // 2 x 2048 floats (dbuf reduction)

    const int tid  = threadIdx.x;
    const int warp = tid >> 5, lane = tid & 31;
    const int wg    = warp >> 2;       // 0 -> K[0,512), 1 -> K[512,1024)
    const int wwarp = warp & 3;        // warp within group (owns 16 N cols)
    const int wtid  = tid & 127;
    const int barid = 1 + wg;
    const int grp = blockIdx.x >> 4;   // batch group (8)
    const int nt  = blockIdx.x & 15;   // N tile within group (16)
    const int m0 = grp * MT;
    const int n0 = nt * NT;

    // ---- prologue: Wm slab -> smem bf16 ----
    for (int i = tid; i < NT * 128; i += THREADS) {
        int r = i >> 7, c8 = i & 127;
        const float4* s = (const float4*)&Wm[(size_t)(n0 + r) * HID + c8 * 8];
        float4 f0 = s[0], f1 = s[1];
        uint32_t pk[4];
        ((__nv_bfloat162*)pk)[0] = __floats2bfloat162_rn(f0.x, f0.y);
        ((__nv_bfloat162*)pk)[1] = __floats2bfloat162_rn(f0.z, f0.w);
        ((__nv_bfloat162*)pk)[2] = __floats2bfloat162_rn(f1.x, f1.y);
        ((__nv_bfloat162*)pk)[3] = __floats2bfloat162_rn(f1.z, f1.w);
        *(uint4*)&wm_s[r * SW + c8 * 8] = *(uint4*)pk;
    }

    // ---- prologue: h0 = b_start broadcast ----
    for (int i = tid; i < MT * (NT / 2); i += THREADS) {
        int r = i >> 5, c2 = i & 31;
        __nv_bfloat162 v = __floats2bfloat162_rn(b_start[n0 + c2 * 2],
                                                 b_start[n0 + c2 * 2 + 1]);
        *(__nv_bfloat162*)&g_hidden[(size_t)(m0 + r) * HID + n0 + c2 * 2] = v;
    }

    // ---- prologue: transpose Wx slice with (bm+bx) folded ----
    {
        float (*tile)[33] = (float (*)[33])xs;
        int x0 = blockIdx.x * 32;
        int tx = lane, ty = warp;        // 32 x 8
        for (int yt = 0; yt < HID / 32; yt++) {
            int y0 = yt * 32;
            for (int i = ty; i < 32; i += 8)
                tile[i][tx] = Wx[(size_t)(y0 + i) * N_IN + x0 + tx];
            __syncthreads();
            for (int i = ty; i < 32; i += 8)
                g_WxT[(size_t)(x0 + i) * HID + y0 + tx] = tile[tx][i] + bm[y0 + tx] + bx[y0 + tx];
            __syncthreads();
        }
    }
    __threadfence();
    grid_barrier(tid);   // WxT + h0 visible everywhere

    // ldmatrix lane bases (per warp: M32 x N16)
    const uint32_t a_lane = smem_u32(a_s) +
        (uint32_t)(((lane & 15) * SW + ((lane >> 4) << 3)) * 2);
    const uint32_t b_lane = smem_u32(wm_s) +
        (uint32_t)(((wwarp * 16 + (lane & 15)) * SW + ((lane >> 4) << 3)) * 2);
    const int cp_row = wtid >> 2, cp_q4 = wtid & 3;
    const uint32_t cp_dst_row = smem_u32(a_s) + (uint32_t)(cp_row * SW * 2);
    const int mych = nt >> 2;            // the K-chunk this CTA's output belongs to

    // ---- mainloop: per-chunk dataflow pipeline ----
    for (int t = 0; t < T_STEPS; t++) {
        // wg0 gathers x projection (it alone runs the epilogue)
        if (wg == 0) {
            const int r = wtid >> 2, seg = wtid & 3;
            int x = x_idx[t * BATCH + m0 + r];
            const float4* src = (const float4*)&g_WxT[(size_t)x * HID + n0 + seg * 16];
            float4* dst = (float4*)&xs[r * XW + seg * 16];
            dst[0] = src[0]; dst[1] = src[1]; dst[2] = src[2]; dst[3] = src[3];
        }

        // each warpgroup: gate+load its 2 K-chunks (pipelined across producers)
        const __nv_bfloat16* rowp = g_hidden + (size_t)t * BATCH * HID
                                  + (size_t)(m0 + cp_row) * HID;
        const int* fbase = &g_ready[(t * GROUPS + grp) * 4];
        #pragma unroll
        for (int c = 0; c < 2; c++) {
            int gch = wg * 2 + c;
            if (t > 0) {
                if (wtid == 0) { while (ld_acq(fbase + gch) < 4) { } }
                bar_named(barid);           // broadcast readiness to the warpgroup
            }
            #pragma unroll
            for (int q = 0; q < 8; q++) {
                int c8 = gch * 32 + cp_q4 * 8 + q;
                cp16(cp_dst_row + (uint32_t)(c8 * 16), rowp + c8 * 8);
            }
            asm volatile("cp.async.commit_group;" ::: "memory");
        }

        float acc[2][2][4];
        #pragma unroll
        for (int i = 0; i < 2; i++)
            #pragma unroll
            for (int j = 0; j < 2; j++)
                acc[i][j][0] = acc[i][j][1] = acc[i][j][2] = acc[i][j][3] = 0.f;

        #pragma unroll
        for (int c = 0; c < 2; c++) {
            if (c == 0) asm volatile("cp.async.wait_group 1;" ::: "memory");
            else        asm volatile("cp.async.wait_group 0;" ::: "memory");
            bar_named(barid);

            #pragma unroll
            for (int kk = 0; kk < KC; kk += 16) {
                const uint32_t kb = (uint32_t)(((wg * 2 + c) * KC + kk) * 2);
                uint32_t a0, a1, a2, a3, a4, a5, a6, a7, b0, b1, b2, b3;
                ldmx4(a0, a1, a2, a3, a_lane + kb);                           // rows 0-15
                ldmx4(a4, a5, a6, a7, a_lane + (uint32_t)(16 * SW * 2) + kb); // rows 16-31
                ldmx4(b0, b1, b2, b3, b_lane + kb);                           // 16 n-cols
                mma16816(acc[0][0], a0, a1, a2, a3, b0, b2);
                mma16816(acc[0][1], a0, a1, a2, a3, b1, b3);
                mma16816(acc[1][0], a4, a5, a6, a7, b0, b2);
                mma16816(acc[1][1], a4, a5, a6, a7, b1, b3);
            }
        }

        // K-split handoff: wg1 -> red (double-buffered); ONE CTA barrier per step
        float* rbuf = red + (t & 1) * 2048;
        float* af = &acc[0][0][0];
        if (wg == 1) {
            #pragma unroll
            for (int j = 0; j < 16; j++) rbuf[j * 128 + wtid] = af[j];
        }
        __syncthreads();

        if (wg == 0) {
            #pragma unroll
            for (int j = 0; j < 16; j++) af[j] += rbuf[j * 128 + wtid];

            // epilogue: + xproj(+bias), tanh.approx, pack bf16, store h[t+1]
            __nv_bfloat16* hout = g_hidden + (size_t)(t + 1) * BATCH * HID;
            const int r_base = lane >> 2;
            const int c_base = (lane & 3) * 2;
            #pragma unroll
            for (int mi = 0; mi < 2; mi++) {
                #pragma unroll
                for (int ni = 0; ni < 2; ni++) {
                    int col = wwarp * 16 + ni * 8 + c_base;
                    #pragma unroll
                    for (int half = 0; half < 2; half++) {
                        int row = mi * 16 + r_base + half * 8;
                        float v0 = acc[mi][ni][half * 2 + 0] + xs[row * XW + col];
                        float v1 = acc[mi][ni][half * 2 + 1] + xs[row * XW + col + 1];
                        asm("tanh.approx.f32 %0, %0;" : "+f"(v0));
                        asm("tanh.approx.f32 %0, %0;" : "+f"(v1));
                        *(__nv_bfloat162*)&hout[(size_t)(m0 + row) * HID + n0 + col] =
                            __floats2bfloat162_rn(v0, v1);
                    }
                }
            }
            bar_named(1);          // wg0 stores complete
            if (tid == 0) {
                __threadfence();
                atomicAdd(&g_ready[((t + 1) * GROUPS + grp) * 4 + mych], 1);
            }
        }
    }

    // ---- fused logits / pred / loss ----
    if (tid == 0) {
        const int* f = &g_ready[(T_STEPS * GROUPS + grp) * 4];
        #pragma unroll
        for (int c = 0; c < 4; c++)
            while (ld_acq(f + c) < 4) { }
    }
    __syncthreads();

    for (int i = 0; i < 25; i++) {
        int j  = nt * 200 + warp * 25 + i;   // 0..3199 within group
        int t  = j >> 5;
        int bl = j & 31;
        int gw = t * BATCH + m0 + bl;
        int y  = y_idx[gw];
        const __nv_bfloat16* h = g_hidden + (size_t)(t + 1) * BATCH * HID
                               + (size_t)(m0 + bl) * HID;
        const float* wy = Wy + (size_t)y * HID;
        float acc = 0.f;
        #pragma unroll
        for (int p = 0; p < 4; p++) {
            int k = p * 256 + lane * 8;
            uint4 hv = *(const uint4*)(h + k);
            const float4* w4 = (const float4*)(wy + k);
            float4 w0 = w4[0], w1 = w4[1];
            const __nv_bfloat162* hb = (const __nv_bfloat162*)&hv;
            float2 f0 = __bfloat1622float2(hb[0]);
            float2 f1 = __bfloat1622float2(hb[1]);
            float2 f2 = __bfloat1622float2(hb[2]);
            float2 f3 = __bfloat1622float2(hb[3]);
            acc += f0.x * w0.x + f0.y * w0.y + f1.x * w0.z + f1.y * w0.w
                 + f2.x * w1.x + f2.y * w1.y + f3.x * w1.z + f3.y * w1.w;
        }
        #pragma unroll
        for (int o = 16; o; o >>= 1) acc += __shfl_xor_sync(0xffffffffu, acc, o);
        if (lane == 0) {
            float logit = acc + by[y];
            float pred = 1.f / (1.f + expf(-logit));
            float tr = truth[gw];
            float lsp = fminf(logit, 0.f)  - log1pf(expf(-fabsf(logit)));
            float lsn = fminf(-logit, 0.f) - log1pf(expf(-fabsf(logit)));
            out[gw] = pred;
            out[T_STEPS * BATCH + gw] = -(tr * lsp + (1.f - tr) * lsn);
        }
    }

    // ---- reset arrive counters for the next graph replay ----
    grid_barrier(tid);     // nobody still polling
    for (int i = blockIdx.x * THREADS + tid; i < (T_STEPS + 1) * GROUPS * 4;
         i += NCTA * THREADS)
        g_ready[i] = 0;
    __threadfence();
    grid_barrier(tid);     // resets visible before exit
}

// ---------------- launch ----------------
extern "C" void kernel_launch(void* const* d_in, const int* in_sizes, int n_in,
                              void* d_out, int out_size) {
    (void)in_sizes; (void)n_in; (void)out_size;
    const int*   x_idx   = (const int*)d_in[0];
    const int*   y_idx   = (const int*)d_in[1];
    const float* truth   = (const float*)d_in[2];
    const float* Wm      = (const float*)d_in[3];
    const float* bm      = (const float*)d_in[4];
    const float* Wx      = (const float*)d_in[5];
    const float* bx      = (const float*)d_in[6];
    const float* Wy      = (const float*)d_in[7];
    const float* by      = (const float*)d_in[8];
    // d_in[9] = W_start: multiplied by zeros -> unused
    const float* b_start = (const float*)d_in[10];
    float* out = (float*)d_out;

    // smem: Wm slab + A tile + xs + double-buffered reduction = ~218 KB
    const int smem_bytes = (NT * SW + MT * SW) * 2 + (MT * XW + 2 * 2048) * 4;
    cudaFuncSetAttribute(rnn_kernel, cudaFuncAttributeMaxDynamicSharedMemorySize, smem_bytes);
    rnn_kernel<<<NCTA, THREADS, smem_bytes>>>(x_idx, y_idx, truth, Wm, bm, Wx, bx,
                                              Wy, by, b_start, out);
}

// round 9
// speedup vs baseline: 1.5246x; 1.1578x over previous
#include <cuda_runtime.h>
#include <cuda_bf16.h>
#include <cstdint>
#include <cstddef>

#define T_STEPS 100
#define BATCH   256
#define HID     1024
#define N_IN    4096

#define NCTA    128
#define THREADS 512
#define GROUPS  8          // batch groups (32 rows each)
#define GSZ     16         // CTAs per group (N tiles)
#define MT      32         // batch rows per group
#define NT      64         // hidden cols per CTA
#define KC      256        // K chunk per warpgroup
#define SW      1032       // A smem row stride in bf16 (conflict-free ldmatrix)
#define XW      68         // xs row stride in floats
#define RSTRIDE 20         // red row stride in floats (16B-aligned, conflict-free)
#define REDSZ   (3 * 128 * RSTRIDE)   // floats per red buffer

// ---------------- device scratch ----------------
__device__ __nv_bfloat16 g_hidden[(size_t)(T_STEPS + 1) * BATCH * HID];
__device__ float         g_WxT[(size_t)N_IN * HID];             // Wx^T with (bm+bx) folded
__device__ int           g_ready[(T_STEPS + 1) * GROUPS * 4];   // per-chunk arrive counters
__device__ unsigned      g_count;                               // full-grid barrier
__device__ unsigned      g_gen;

// ---------------- helpers ----------------
__device__ __forceinline__ uint32_t smem_u32(const void* p) {
    return (uint32_t)__cvta_generic_to_shared(p);
}
__device__ __forceinline__ void ldmx4(uint32_t& r0, uint32_t& r1, uint32_t& r2, uint32_t& r3,
                                      uint32_t addr) {
    asm volatile("ldmatrix.sync.aligned.m8n8.x4.shared.b16 {%0,%1,%2,%3},[%4];\n"
                 : "=r"(r0), "=r"(r1), "=r"(r2), "=r"(r3) : "r"(addr));
}
__device__ __forceinline__ void mma16816(float* c, uint32_t a0, uint32_t a1, uint32_t a2,
                                         uint32_t a3, uint32_t b0, uint32_t b1) {
    asm volatile("mma.sync.aligned.m16n8k16.row.col.f32.bf16.bf16.f32 "
                 "{%0,%1,%2,%3},{%4,%5,%6,%7},{%8,%9},{%0,%1,%2,%3};\n"
                 : "+f"(c[0]), "+f"(c[1]), "+f"(c[2]), "+f"(c[3])
                 : "r"(a0), "r"(a1), "r"(a2), "r"(a3), "r"(b0), "r"(b1));
}
__device__ __forceinline__ void cp16(uint32_t dst, const void* src) {
    asm volatile("cp.async.cg.shared.global [%0],[%1],16;\n" :: "r"(dst), "l"(src));
}
__device__ __forceinline__ int ld_acq(const int* p) {
    int v;
    asm volatile("ld.acquire.gpu.global.b32 %0,[%1];" : "=r"(v) : "l"(p) : "memory");
    return v;
}
__device__ __forceinline__ void bar_sync(int id, int cnt) {
    asm volatile("bar.sync %0, %1;" :: "r"(id), "r"(cnt) : "memory");
}
__device__ __forceinline__ void bar_arrive(int id, int cnt) {
    asm volatile("bar.arrive %0, %1;" :: "r"(id), "r"(cnt) : "memory");
}

__device__ __forceinline__ void grid_barrier(int tid) {
    __syncthreads();
    if (tid == 0) {
        __threadfence();
        unsigned gen = atomicAdd(&g_gen, 0u);
        unsigned old = atomicAdd(&g_count, 1u);
        if (old == NCTA - 1) {
            atomicExch(&g_count, 0u);
            __threadfence();
            atomicAdd(&g_gen, 1u);
        } else {
            while (*(volatile unsigned*)&g_gen == gen) { }
        }
        __threadfence();
    }
    __syncthreads();
}

// ---------------- single fused persistent kernel ----------------
__global__ void __launch_bounds__(THREADS, 1) rnn_kernel(
    const int* __restrict__ x_idx, const int* __restrict__ y_idx,
    const float* __restrict__ truth, const float* __restrict__ Wm,
    const float* __restrict__ bm, const float* __restrict__ Wx,
    const float* __restrict__ bx, const float* __restrict__ Wy,
    const float* __restrict__ by, const float* __restrict__ b_start,
    float* __restrict__ out) {
    extern __shared__ __align__(16) char smem_raw[];
    __nv_bfloat16* a_s = (__nv_bfloat16*)smem_raw;        // 32 x SW bf16 (full h tile)
    float*         xs  = (float*)(a_s + MT * SW);         // 32 x XW floats (+xpose stage)
    float*         red = xs + MT * XW;                    // 2 x REDSZ floats (dbuf partials)

    const int tid  = threadIdx.x;
    const int warp = tid >> 5, lane = tid & 31;
    const int wg   = warp >> 2;        // K chunk this warpgroup owns (0..3)
    const int nw   = warp & 3;         // N16 subtile within CTA (0..3)
    const int wtid = tid & 127;
    const int grp = blockIdx.x >> 4;   // batch group (8)
    const int nt  = blockIdx.x & 15;   // N tile within group (16)
    const int m0 = grp * MT;
    const int n0 = nt * NT;

    // ---- prologue: h0 = b_start broadcast ----
    for (int i = tid; i < MT * (NT / 2); i += THREADS) {
        int r = i >> 5, c2 = i & 31;
        __nv_bfloat162 v = __floats2bfloat162_rn(b_start[n0 + c2 * 2],
                                                 b_start[n0 + c2 * 2 + 1]);
        *(__nv_bfloat162*)&g_hidden[(size_t)(m0 + r) * HID + n0 + c2 * 2] = v;
    }

    // ---- prologue: transpose Wx slice with (bm+bx) folded ----
    {
        float (*tile)[33] = (float (*)[33])xs;
        int x0 = blockIdx.x * 32;
        int tx = lane, ty = warp;        // 32 x 16
        for (int yt = 0; yt < HID / 32; yt++) {
            int y0 = yt * 32;
            for (int i = ty; i < 32; i += 16)
                tile[i][tx] = Wx[(size_t)(y0 + i) * N_IN + x0 + tx];
            __syncthreads();
            for (int i = ty; i < 32; i += 16)
                g_WxT[(size_t)(x0 + i) * HID + y0 + tx] = tile[tx][i] + bm[y0 + tx] + bx[y0 + tx];
            __syncthreads();
        }
    }

    // ---- prologue: preload B fragments (Wm) into registers, ONCE ----
    // warp covers N16 (cols n0+nw*16..+16) x K256 (cols wg*256..+256)
    // mma m16n8k16 B-frag: b = pack(Wm[n][k], Wm[n][k+1]); n = lane>>2 (+8), k = (lane&3)*2 (+8)
    uint32_t breg[16][4];
    {
        const int nb = n0 + nw * 16 + (lane >> 2);
        const int kb = wg * KC + (lane & 3) * 2;
        #pragma unroll
        for (int kk = 0; kk < 16; kk++) {
            #pragma unroll
            for (int j = 0; j < 4; j++) {
                const float2 v = *(const float2*)&Wm[(size_t)(nb + (j >> 1) * 8) * HID
                                                     + kb + kk * 16 + (j & 1) * 8];
                ((__nv_bfloat162*)&breg[kk][j])[0] = __floats2bfloat162_rn(v.x, v.y);
            }
        }
    }
    __threadfence();
    grid_barrier(tid);   // WxT + h0 visible everywhere

    // A ldmatrix lane base (row = lane&15, k-half = lane>>4)
    const uint32_t a_lane = smem_u32(a_s) +
        (uint32_t)(((lane & 15) * SW + ((lane >> 4) << 3)) * 2);
    const int cp_row = wtid >> 2, cp_q4 = wtid & 3;
    const uint32_t cp_dst_row = smem_u32(a_s) + (uint32_t)(cp_row * SW * 2);
    const int mych = nt >> 2;            // the K-chunk this CTA's output belongs to

    // ---- mainloop: per-chunk dataflow, zero CTA-wide barriers ----
    for (int t = 0; t < T_STEPS; t++) {
        // wg0 gathers x projection (it alone runs the epilogue)
        if (wg == 0) {
            const int r = wtid >> 2, seg = wtid & 3;
            int x = x_idx[t * BATCH + m0 + r];
            const float4* src = (const float4*)&g_WxT[(size_t)x * HID + n0 + seg * 16];
            float4* dst = (float4*)&xs[r * XW + seg * 16];
            dst[0] = src[0]; dst[1] = src[1]; dst[2] = src[2]; dst[3] = src[3];
        }

        // gate + load THIS warpgroup's K-chunk (M32 x 256 cols = 16KB)
        if (t > 0) {
            if (wtid == 0) {
                const int* f = &g_ready[(t * GROUPS + grp) * 4 + wg];
                while (ld_acq(f) < 4) { }
            }
            bar_sync(1 + wg, 128);
        }
        {
            const __nv_bfloat16* rowp = g_hidden + (size_t)t * BATCH * HID
                                      + (size_t)(m0 + cp_row) * HID;
            #pragma unroll
            for (int q = 0; q < 8; q++) {
                int c8 = wg * 32 + cp_q4 * 8 + q;
                cp16(cp_dst_row + (uint32_t)(c8 * 16), rowp + c8 * 8);
            }
            asm volatile("cp.async.commit_group;" ::: "memory");
            asm volatile("cp.async.wait_group 0;" ::: "memory");
            bar_sync(1 + wg, 128);
        }

        // MMA: A from smem (2 ldmx4/iter), B from registers
        float acc[2][2][4];
        #pragma unroll
        for (int i = 0; i < 2; i++)
            #pragma unroll
            for (int j = 0; j < 2; j++)
                acc[i][j][0] = acc[i][j][1] = acc[i][j][2] = acc[i][j][3] = 0.f;
        #pragma unroll
        for (int kk = 0; kk < 16; kk++) {
            const uint32_t kbyte = (uint32_t)((wg * KC + kk * 16) * 2);
            uint32_t a0, a1, a2, a3, a4, a5, a6, a7;
            ldmx4(a0, a1, a2, a3, a_lane + kbyte);                            // rows 0-15
            ldmx4(a4, a5, a6, a7, a_lane + (uint32_t)(16 * SW * 2) + kbyte);  // rows 16-31
            mma16816(acc[0][0], a0, a1, a2, a3, breg[kk][0], breg[kk][1]);
            mma16816(acc[0][1], a0, a1, a2, a3, breg[kk][2], breg[kk][3]);
            mma16816(acc[1][0], a4, a5, a6, a7, breg[kk][0], breg[kk][1]);
            mma16816(acc[1][1], a4, a5, a6, a7, breg[kk][2], breg[kk][3]);
        }

        float* af = &acc[0][0][0];
        float* rbuf = red + (t & 1) * REDSZ;
        if (wg != 0) {
            // publish partials (aligned float4, conflict-free stride 20) and run ahead
            float4* dst = (float4*)&rbuf[((wg - 1) * 128 + wtid) * RSTRIDE];
            #pragma unroll
            for (int q = 0; q < 4; q++) dst[q] = ((const float4*)af)[q];
            bar_arrive(5, THREADS);
        } else {
            bar_sync(5, THREADS);   // wait for wgs 1-3 partials
            #pragma unroll
            for (int p = 0; p < 3; p++) {
                const float4* src = (const float4*)&rbuf[(p * 128 + wtid) * RSTRIDE];
                #pragma unroll
                for (int q = 0; q < 4; q++) {
                    float4 v = src[q];
                    af[q * 4 + 0] += v.x; af[q * 4 + 1] += v.y;
                    af[q * 4 + 2] += v.z; af[q * 4 + 3] += v.w;
                }
            }

            // epilogue: + xproj(+bias), tanh.approx, pack bf16, store h[t+1]
            __nv_bfloat16* hout = g_hidden + (size_t)(t + 1) * BATCH * HID;
            const int r_base = lane >> 2;
            const int c_base = (lane & 3) * 2;
            #pragma unroll
            for (int mi = 0; mi < 2; mi++) {
                #pragma unroll
                for (int ni = 0; ni < 2; ni++) {
                    int col = nw * 16 + ni * 8 + c_base;
                    #pragma unroll
                    for (int half = 0; half < 2; half++) {
                        int row = mi * 16 + r_base + half * 8;
                        float v0 = acc[mi][ni][half * 2 + 0] + xs[row * XW + col];
                        float v1 = acc[mi][ni][half * 2 + 1] + xs[row * XW + col + 1];
                        asm("tanh.approx.f32 %0, %0;" : "+f"(v0));
                        asm("tanh.approx.f32 %0, %0;" : "+f"(v1));
                        *(__nv_bfloat162*)&hout[(size_t)(m0 + row) * HID + n0 + col] =
                            __floats2bfloat162_rn(v0, v1);
                    }
                }
            }
            bar_sync(1, 128);       // wg0 stores complete
            if (wtid == 0) {
                __threadfence();
                atomicAdd(&g_ready[((t + 1) * GROUPS + grp) * 4 + mych], 1);
            }
        }
    }

    // ---- fused logits / pred / loss ----
    if (tid == 0) {
        const int* f = &g_ready[(T_STEPS * GROUPS + grp) * 4];
        #pragma unroll
        for (int c = 0; c < 4; c++)
            while (ld_acq(f + c) < 4) { }
    }
    __syncthreads();

    for (int i = 0; i < 13; i++) {
        int j = i * 16 + warp;               // 0..199 within CTA (200 samples/CTA)
        if (j >= 200) break;
        int jj = nt * 200 + j;               // 0..3199 within group
        int t  = jj >> 5;
        int bl = jj & 31;
        int gw = t * BATCH + m0 + bl;
        int y  = y_idx[gw];
        const __nv_bfloat16* h = g_hidden + (size_t)(t + 1) * BATCH * HID
                               + (size_t)(m0 + bl) * HID;
        const float* wy = Wy + (size_t)y * HID;
        float acc = 0.f;
        #pragma unroll
        for (int p = 0; p < 4; p++) {
            int k = p * 256 + lane * 8;
            uint4 hv = *(const uint4*)(h + k);
            const float4* w4 = (const float4*)(wy + k);
            float4 w0 = w4[0], w1 = w4[1];
            const __nv_bfloat162* hb = (const __nv_bfloat162*)&hv;
            float2 f0 = __bfloat1622float2(hb[0]);
            float2 f1 = __bfloat1622float2(hb[1]);
            float2 f2 = __bfloat1622float2(hb[2]);
            float2 f3 = __bfloat1622float2(hb[3]);
            acc += f0.x * w0.x + f0.y * w0.y + f1.x * w0.z + f1.y * w0.w
                 + f2.x * w1.x + f2.y * w1.y + f3.x * w1.z + f3.y * w1.w;
        }
        #pragma unroll
        for (int o = 16; o; o >>= 1) acc += __shfl_xor_sync(0xffffffffu, acc, o);
        if (lane == 0) {
            float logit = acc + by[y];
            float pred = 1.f / (1.f + expf(-logit));
            float tr = truth[gw];
            float lsp = fminf(logit, 0.f)  - log1pf(expf(-fabsf(logit)));
            float lsn = fminf(-logit, 0.f) - log1pf(expf(-fabsf(logit)));
            out[gw] = pred;
            out[T_STEPS * BATCH + gw] = -(tr * lsp + (1.f - tr) * lsn);
        }
    }

    // ---- reset arrive counters for the next graph replay ----
    grid_barrier(tid);     // nobody still polling
    for (int i = blockIdx.x * THREADS + tid; i < (T_STEPS + 1) * GROUPS * 4;
         i += NCTA * THREADS)
        g_ready[i] = 0;
    __threadfence();
    grid_barrier(tid);     // resets visible before exit
}

// ---------------- launch ----------------
extern "C" void kernel_launch(void* const* d_in, const int* in_sizes, int n_in,
                              void* d_out, int out_size) {
    (void)in_sizes; (void)n_in; (void)out_size;
    const int*   x_idx   = (const int*)d_in[0];
    const int*   y_idx   = (const int*)d_in[1];
    const float* truth   = (const float*)d_in[2];
    const float* Wm      = (const float*)d_in[3];
    const float* bm      = (const float*)d_in[4];
    const float* Wx      = (const float*)d_in[5];
    const float* bx      = (const float*)d_in[6];
    const float* Wy      = (const float*)d_in[7];
    const float* by      = (const float*)d_in[8];
    // d_in[9] = W_start: multiplied by zeros -> unused
    const float* b_start = (const float*)d_in[10];
    float* out = (float*)d_out;

    // smem: A tile + xs + double-buffered reduction = ~135 KB
    const int smem_bytes = MT * SW * 2 + (MT * XW + 2 * REDSZ) * 4;
    cudaFuncSetAttribute(rnn_kernel, cudaFuncAttributeMaxDynamicSharedMemorySize, smem_bytes);
    rnn_kernel<<<NCTA, THREADS, smem_bytes>>>(x_idx, y_idx, truth, Wm, bm, Wx, bx,
                                              Wy, by, b_start, out);
}